// round 16
// baseline (speedup 1.0000x reference)
#include <cuda_runtime.h>
#include <cuda_fp16.h>
#include <math.h>

#define B_  16
#define L_  4096
#define E_  128
#define F_  256
#define Y_  1000
#define YP_ 1024
#define MP_ 2048             /* padded, interleaved attn M */

#define BM  128
#define BN  128
#define BK  64               /* halves per K chunk */
#define SROWH 72             /* staging row stride in halves (144B) */
#define STAGEH (BM * SROWH)  /* stage halves = 9216 */
#define NSTAGE 3
#define CV_SMEM (2 * NSTAGE * STAGEH * 2)   /* conv: A+B, 3 stages = 110592 B */

/* attn: B resident (128 x 264 halves) + A 2-stage (128 x 72 halves each) */
#define SROWB 264
#define AT_BH (BN * SROWB)                   /* 33792 halves */
#define AT_SMEM ((AT_BH + 2 * STAGEH) * 2)   /* 104448 B */

#define FUSE_SMEM (CV_SMEM > AT_SMEM ? CV_SMEM : AT_SMEM)

/* fused-kernel block layout */
#define NEMB   8192          /* embed gather blocks */
#define NWH    128           /* conv_w transpose blocks */
#define NW2    512           /* weight stack blocks */
#define PREP_T (NEMB + NWH + NW2)     /* 8832 */
#define NCONV  1024
#define CONV0  PREP_T                  /* 8832 */
#define ATTN0  (CONV0 + NCONV)         /* 9856 */
#define NBLK   (ATTN0 + 2048)          /* 11904 */

// Scratch (static __device__ arrays; allocation-free per harness rules)
__device__ __align__(128) __half g_embH[(size_t)B_ * L_ * E_];  // fp16 embeddings
__device__ __align__(128) __half g_wH  [3 * F_ * E_];           // fp16 conv_w [kw][f][e]
__device__ __align__(128) __half g_w2H [(size_t)MP_ * F_];      // interleaved [U;fc] rows
__device__ __align__(128) __half g_hcH [(size_t)B_ * L_ * F_];  // conv out fp16 [b][l][f]
__device__ __align__(128) float  g_part[(size_t)B_ * YP_ * 64 * 3]; // (m,Z,S) partials
__device__ int g_flag[B_ * 32];     // conv tile-ready flags (2 arrivals each)
__device__ int g_emb_done[B_];      // embed blocks done per batch (512 each)
__device__ int g_wh_done;           // wH blocks done (128)
__device__ int g_w2_done;           // w2H blocks done (512)
__device__ float g_nll[B_];

// ---------------------------------------------------------------------------
__device__ __forceinline__ unsigned smem_u32(const void* p) {
    unsigned a;
    asm("{ .reg .u64 t; cvta.to.shared.u64 t, %1; cvt.u32.u64 %0, t; }"
        : "=r"(a) : "l"(p));
    return a;
}
__device__ __forceinline__ void cp_async16(unsigned dst, const void* src, int src_bytes) {
    asm volatile("cp.async.cg.shared.global [%0], [%1], 16, %2;"
                 :: "r"(dst), "l"(src), "r"(src_bytes));
}
__device__ __forceinline__ void cp_commit() {
    asm volatile("cp.async.commit_group;");
}
__device__ __forceinline__ void ldsm4(unsigned* r, unsigned addr) {
    asm volatile("ldmatrix.sync.aligned.m8n8.x4.shared.b16 {%0,%1,%2,%3}, [%4];"
                 : "=r"(r[0]), "=r"(r[1]), "=r"(r[2]), "=r"(r[3]) : "r"(addr));
}
__device__ __forceinline__ void mma16816(float* d, const unsigned* a, const unsigned* b) {
    asm volatile(
        "mma.sync.aligned.m16n8k16.row.col.f32.f16.f16.f32 "
        "{%0,%1,%2,%3}, {%4,%5,%6,%7}, {%8,%9}, {%0,%1,%2,%3};"
        : "+f"(d[0]), "+f"(d[1]), "+f"(d[2]), "+f"(d[3])
        : "r"(a[0]), "r"(a[1]), "r"(a[2]), "r"(a[3]), "r"(b[0]), "r"(b[1]));
}
__device__ __forceinline__ void spin_ge(int* ctr, int want) {
    while (atomicAdd(ctr, 0) < want) __nanosleep(64);
}

// ---------------------------------------------------------------------------
// MEGA kernel: prep + conv + attn, dependency-gated via counters/flags.
//  bids [0,8192):        embed gather (8 l's per block) -> g_emb_done[b]
//  bids [8192,8320):     conv_w transpose -> g_wh_done
//  bids [8320,8832):     interleaved weight stack -> g_w2_done
//  bids [8832,9856):     conv (waits wh + emb[b]); publishes g_flag tile
//  bids [9856,11904):    attn (waits w2 + conv tile flag)
// ---------------------------------------------------------------------------
__global__ __launch_bounds__(256)
void mega_kernel(const int* __restrict__ x,
                 const float* __restrict__ embed_w,
                 const float* __restrict__ conv_w,
                 const float* __restrict__ U_w,
                 const float* __restrict__ fc_w,
                 const float* __restrict__ bias)
{
    extern __shared__ __align__(16) char smem[];

    int tid  = threadIdx.x;
    int wid  = tid >> 5, lane = tid & 31;
    int g    = lane >> 2, tig = lane & 3;
    int lq   = lane >> 3, lr  = lane & 7;
    int wm   = wid >> 1,  wn  = wid & 1;
    int blk  = blockIdx.x;

    if (blk < NEMB) {
        // =================== EMBED gather ===================
        int b = blk >> 9;
        int l = (blk & 511) * 8 + (tid >> 5);
        int q = lane;
        int xi = x[b * L_ + l];
        float4 v = ((const float4*)(embed_w + (size_t)xi * E_))[q];
        __half2 h01 = __floats2half2_rn(v.x, v.y);
        __half2 h23 = __floats2half2_rn(v.z, v.w);
        uint2 u;
        u.x = *(unsigned*)&h01;
        u.y = *(unsigned*)&h23;
        ((uint2*)(g_embH + ((size_t)b * L_ + l) * E_))[q] = u;

        __syncthreads();
        __threadfence();
        if (tid == 0) atomicAdd(&g_emb_done[b], 1);

    } else if (blk < NEMB + NWH) {
        // =================== conv_w transpose ===================
        int i = (blk - NEMB) * 256 + tid;
        if (i < F_ * E_) {
            int f = i / E_, e = i % E_;
            #pragma unroll
            for (int kw = 0; kw < 3; kw++)
                g_wH[((size_t)kw * F_ + f) * E_ + e] =
                    __float2half_rn(conv_w[((size_t)f * E_ + e) * 3 + kw]);
        }
        __syncthreads();
        __threadfence();
        if (tid == 0) atomicAdd(&g_wh_done, 1);

    } else if (blk < PREP_T) {
        // =================== weight stack ===================
        int i = (blk - NEMB - NWH) * 256 + tid;
        if (i < MP_ * F_ / 4) {
            int r = i / (F_ / 4), c4 = i % (F_ / 4);
            float4 v = make_float4(0.f, 0.f, 0.f, 0.f);
            if (r < 2 * Y_) {
                int y = r >> 1;
                const float* src = (r & 1) ? fc_w : U_w;
                v = ((const float4*)(src + (size_t)y * F_))[c4];
            }
            __half2 h01 = __floats2half2_rn(v.x, v.y);
            __half2 h23 = __floats2half2_rn(v.z, v.w);
            uint2 u;
            u.x = *(unsigned*)&h01;
            u.y = *(unsigned*)&h23;
            ((uint2*)(g_w2H + (size_t)r * F_))[c4] = u;
        }
        __syncthreads();
        __threadfence();
        if (tid == 0) atomicAdd(&g_w2_done, 1);

    } else if (blk < ATTN0) {
        // =================== CONV path (R14-proven body) ===================
        unsigned aBase = smem_u32(smem);
        unsigned bBase = aBase + NSTAGE * STAGEH * 2;

        int cb  = blk - CONV0;
        int xt  = cb & 31;             // l-tile
        int yt  = (cb >> 5) & 1;       // f-tile
        int b   = cb >> 6;
        int m0  = xt * BM, n0 = yt * BN;
        const int nchunks = 6;

        if (tid == 0) {
            spin_ge(&g_wh_done, NWH);
            spin_ge(&g_emb_done[b], 512);
        }
        __syncthreads();

        int lrow  = tid >> 1;
        int lcolh = (tid & 1) * 32;

        float d[2][8][4];
        #pragma unroll
        for (int mi = 0; mi < 2; mi++)
            #pragma unroll
            for (int ni = 0; ni < 8; ni++)
                #pragma unroll
                for (int q = 0; q < 4; q++) d[mi][ni][q] = 0.0f;

        auto prefetch = [&](int c) {
            int st = c % NSTAGE;
            int kw = c >> 1, ek = (c & 1) * BK;
            int lsrc = m0 + lrow + kw - 1;
            bool av = ((unsigned)lsrc < (unsigned)L_);
            int abytes = av ? 16 : 0;
            const __half* ap = g_embH + ((size_t)b * L_ + (av ? lsrc : 0)) * E_ + ek + lcolh;
            const __half* bp = g_wH + ((size_t)kw * F_ + n0 + lrow) * E_ + ek + lcolh;
            unsigned da = aBase + (st * STAGEH + lrow * SROWH + lcolh) * 2;
            unsigned db = bBase + (st * STAGEH + lrow * SROWH + lcolh) * 2;
            #pragma unroll
            for (int j = 0; j < 4; j++) {
                cp_async16(da + j * 16, ap + j * 8, abytes);
                cp_async16(db + j * 16, bp + j * 8, 16);
            }
        };

        prefetch(0); cp_commit();
        prefetch(1); cp_commit();

        unsigned aOffs[2], bOffs[4];
        #pragma unroll
        for (int mi = 0; mi < 2; mi++) {
            int row = wm * 32 + mi * 16 + (lq & 1) * 8 + lr;
            aOffs[mi] = (row * SROWH + (lq >> 1) * 8) * 2;
        }
        #pragma unroll
        for (int ti = 0; ti < 4; ti++) {
            int row = wn * 64 + ti * 16 + (lq >> 1) * 8 + lr;
            bOffs[ti] = (row * SROWH + (lq & 1) * 8) * 2;
        }

        for (int c = 0; c < nchunks; c++) {
            if (c + 1 < nchunks) asm volatile("cp.async.wait_group 1;");
            else                 asm volatile("cp.async.wait_group 0;");
            __syncthreads();
            if (c + 2 < nchunks) { prefetch(c + 2); cp_commit(); }

            int st = c % NSTAGE;
            unsigned Ab = aBase + st * STAGEH * 2;
            unsigned Bb = bBase + st * STAGEH * 2;

            #pragma unroll
            for (int kk = 0; kk < 4; kk++) {
                unsigned af[2][4];
                #pragma unroll
                for (int mi = 0; mi < 2; mi++)
                    ldsm4(af[mi], Ab + aOffs[mi] + kk * 32);
                unsigned bf[4][4];
                #pragma unroll
                for (int ti = 0; ti < 4; ti++)
                    ldsm4(bf[ti], Bb + bOffs[ti] + kk * 32);
                #pragma unroll
                for (int mi = 0; mi < 2; mi++)
                    #pragma unroll
                    for (int ni = 0; ni < 8; ni++)
                        mma16816(d[mi][ni], af[mi], &bf[ni >> 1][(ni & 1) * 2]);
            }
        }

        #pragma unroll
        for (int mi = 0; mi < 2; mi++) {
            int row = m0 + wm * 32 + mi * 16 + g;
            #pragma unroll
            for (int ni = 0; ni < 8; ni++) {
                int col = n0 + wn * 64 + ni * 8 + tig * 2;
                float b0 = bias[col], b1 = bias[col + 1];
                __half2 v0 = __floats2half2_rn(fmaxf(d[mi][ni][0] + b0, 0.f),
                                               fmaxf(d[mi][ni][1] + b1, 0.f));
                __half2 v1 = __floats2half2_rn(fmaxf(d[mi][ni][2] + b0, 0.f),
                                               fmaxf(d[mi][ni][3] + b1, 0.f));
                *(__half2*)(g_hcH + ((size_t)b * L_ + row) * F_ + col)     = v0;
                *(__half2*)(g_hcH + ((size_t)b * L_ + row + 8) * F_ + col) = v1;
            }
        }

        __syncthreads();
        __threadfence();
        if (tid == 0) atomicAdd(&g_flag[b * 32 + xt], 1);

    } else {
        // =================== ATTN path (R14-proven body) ===================
        unsigned bBase = smem_u32(smem);                 // B: 128 x SROWB halves
        unsigned aBase = bBase + AT_BH * 2;              // A: 2 x STAGEH halves

        int ab    = blk - ATTN0;
        int ltile = ab & 31;
        int mgrp  = (ab >> 5) & 3;
        int b     = ab >> 7;
        int n0    = ltile * BN;
        int mg0   = mgrp * 4 * BM;

        if (tid == 0) {
            spin_ge(&g_w2_done, NW2);
            spin_ge(&g_flag[b * 32 + ltile], 2);
        }
        __syncthreads();

        int lrow  = tid >> 1;
        int lcolh = (tid & 1) * 32;

        {
            const __half* bp = g_hcH + ((size_t)b * L_ + n0 + lrow) * F_ + (tid & 1) * 128;
            unsigned db = bBase + (lrow * SROWB + (tid & 1) * 128) * 2;
            #pragma unroll
            for (int j = 0; j < 16; j++)
                cp_async16(db + j * 16, bp + j * 8, 16);
        }
        cp_commit();

        auto prefetchA = [&](int q) {
            int i = q >> 2, kc = q & 3;
            const __half* ap = g_w2H + (size_t)(mg0 + i * BM + lrow) * F_ + kc * BK + lcolh;
            unsigned da = aBase + ((q & 1) * STAGEH + lrow * SROWH + lcolh) * 2;
            #pragma unroll
            for (int j = 0; j < 4; j++)
                cp_async16(da + j * 16, ap + j * 8, 16);
        };

        prefetchA(0);
        cp_commit();

        unsigned aOffs[2], bOffs[4];
        #pragma unroll
        for (int mi = 0; mi < 2; mi++) {
            int row = wm * 32 + mi * 16 + (lq & 1) * 8 + lr;
            aOffs[mi] = (row * SROWH + (lq >> 1) * 8) * 2;
        }
        #pragma unroll
        for (int ti = 0; ti < 4; ti++) {
            int row = wn * 64 + ti * 16 + (lq >> 1) * 8 + lr;
            bOffs[ti] = (row * SROWB + (lq & 1) * 8) * 2;
        }

        int p = ltile * 2 + wn;        // 64-l chunk index (0..63)
        float d[2][8][4];

        for (int q = 0; q < 16; q++) {
            int kc = q & 3;
            if (kc == 0) {
                #pragma unroll
                for (int mi = 0; mi < 2; mi++)
                    #pragma unroll
                    for (int ni = 0; ni < 8; ni++)
                        #pragma unroll
                        for (int u = 0; u < 4; u++) d[mi][ni][u] = 0.0f;
            }

            asm volatile("cp.async.wait_group 0;");
            __syncthreads();
            if (q + 1 < 16) { prefetchA(q + 1); cp_commit(); }

            unsigned Ab = aBase + (q & 1) * STAGEH * 2;
            unsigned Bc = bBase + kc * BK * 2;

            #pragma unroll
            for (int kk = 0; kk < 4; kk++) {
                unsigned af[2][4];
                #pragma unroll
                for (int mi = 0; mi < 2; mi++)
                    ldsm4(af[mi], Ab + aOffs[mi] + kk * 32);
                unsigned bf[4][4];
                #pragma unroll
                for (int ti = 0; ti < 4; ti++)
                    ldsm4(bf[ti], Bc + bOffs[ti] + kk * 32);
                #pragma unroll
                for (int mi = 0; mi < 2; mi++)
                    #pragma unroll
                    for (int ni = 0; ni < 8; ni++)
                        mma16816(d[mi][ni], af[mi], &bf[ni >> 1][(ni & 1) * 2]);
            }

            if (kc == 3) {
                int m0 = mg0 + (q >> 2) * BM;
                #pragma unroll
                for (int mi = 0; mi < 2; mi++) {
                    float td[8][4];
                    #pragma unroll
                    for (int ni = 0; ni < 8; ni++)
                        #pragma unroll
                        for (int u = 0; u < 4; u++)
                            td[ni][u] = __shfl_down_sync(0xFFFFFFFFu, d[mi][ni][u], 4);

                    if ((g & 1) == 0) {
                        #pragma unroll
                        for (int h = 0; h < 2; h++) {
                            float mm = -1e30f, Z = 0.f, S = 0.f;
                            #pragma unroll
                            for (int ni = 0; ni < 8; ni++) {
                                #pragma unroll
                                for (int cq = 0; cq < 2; cq++) {
                                    float sv = d[mi][ni][h * 2 + cq];
                                    float tv = td[ni][h * 2 + cq];
                                    if (sv > mm) {
                                        float r = __expf(mm - sv);
                                        Z *= r; S *= r; mm = sv;
                                    }
                                    float e = __expf(sv - mm);
                                    Z += e; S += e * tv;
                                }
                            }
                            const unsigned qmask = 0x0F0F0F0Fu;
                            #pragma unroll
                            for (int off = 1; off <= 2; off <<= 1) {
                                float m2 = __shfl_xor_sync(qmask, mm, off);
                                float Z2 = __shfl_xor_sync(qmask, Z, off);
                                float S2 = __shfl_xor_sync(qmask, S, off);
                                float mn = fmaxf(mm, m2);
                                float r1 = __expf(mm - mn), r2 = __expf(m2 - mn);
                                Z = Z * r1 + Z2 * r2;
                                S = S * r1 + S2 * r2;
                                mm = mn;
                            }
                            if (tig == 0) {
                                int y = (m0 + wm * 32 + mi * 16 + g + 8 * h) >> 1;
                                float* dst = g_part + ((size_t)(b * YP_ + y) * 64 + p) * 3;
                                dst[0] = mm; dst[1] = Z; dst[2] = S;
                            }
                        }
                    }
                }
            }
        }
    }
}

// ---------------------------------------------------------------------------
// Kernel 2: merge 64 softmax partials per (b,y) -> logits; zero loss slot.
// ---------------------------------------------------------------------------
__global__ void part_reduce_kernel(const float* __restrict__ fc_b,
                                   float* __restrict__ out_logit)
{
    if (blockIdx.x == 0 && threadIdx.x == 0)
        out_logit[B_ * Y_] = 0.0f;          // zero loss accumulator

    int idx = blockIdx.x * 8 + (threadIdx.x >> 5);   // 0..15999
    int b = idx / Y_, y = idx % Y_;
    const float* pp = g_part + ((size_t)(b * YP_ + y) * 64) * 3;
    int lane = threadIdx.x & 31;

    float m = pp[lane * 3], Z = pp[lane * 3 + 1], S = pp[lane * 3 + 2];
    {
        float m2 = pp[(lane + 32) * 3], Z2 = pp[(lane + 32) * 3 + 1], S2 = pp[(lane + 32) * 3 + 2];
        float mn = fmaxf(m, m2);
        float r1 = __expf(m - mn), r2 = __expf(m2 - mn);
        Z = Z * r1 + Z2 * r2; S = S * r1 + S2 * r2; m = mn;
    }
    #pragma unroll
    for (int off = 16; off; off >>= 1) {
        float m2 = __shfl_xor_sync(0xFFFFFFFFu, m, off);
        float Z2 = __shfl_xor_sync(0xFFFFFFFFu, Z, off);
        float S2 = __shfl_xor_sync(0xFFFFFFFFu, S, off);
        float mn = fmaxf(m, m2);
        float r1 = __expf(m - mn), r2 = __expf(m2 - mn);
        Z = Z * r1 + Z2 * r2; S = S * r1 + S2 * r2; m = mn;
    }
    if (lane == 0) out_logit[b * Y_ + y] = S / Z + fc_b[y];
}

// ---------------------------------------------------------------------------
// Kernel 3: per-batch NLL -> atomic accumulate; block 0 resets sync state
// for the next graph replay.
// ---------------------------------------------------------------------------
__global__ void nll_kernel(const float* __restrict__ logit,
                           const int* __restrict__ target,
                           float* __restrict__ loss_out)
{
    if (blockIdx.x == 0) {
        g_flag[threadIdx.x] = 0;
        g_flag[threadIdx.x + 256] = 0;
        if (threadIdx.x < B_) g_emb_done[threadIdx.x] = 0;
        if (threadIdx.x == 0) { g_wh_done = 0; g_w2_done = 0; }
    }

    __shared__ float red[256];
    int b = blockIdx.x;
    int tid = threadIdx.x;
    const float* lr = logit + b * Y_;

    float mx = -1e30f;
    for (int i = tid; i < Y_; i += 256) mx = fmaxf(mx, lr[i]);
    red[tid] = mx; __syncthreads();
    for (int s = 128; s; s >>= 1) {
        if (tid < s) red[tid] = fmaxf(red[tid], red[tid + s]);
        __syncthreads();
    }
    mx = red[0]; __syncthreads();

    float se = 0.0f;
    for (int i = tid; i < Y_; i += 256) se += expf(lr[i] - mx);
    red[tid] = se; __syncthreads();
    for (int s = 128; s; s >>= 1) {
        if (tid < s) red[tid] += red[tid + s];
        __syncthreads();
    }
    if (tid == 0) {
        float lp = lr[target[b]] - mx - logf(red[0]);
        atomicAdd(loss_out, -lp / (float)B_);
    }
}

// ---------------------------------------------------------------------------
extern "C" void kernel_launch(void* const* d_in, const int* in_sizes, int n_in,
                              void* d_out, int out_size)
{
    const int*   x       = (const int*)  d_in[0];
    const int*   target  = (const int*)  d_in[1];
    const float* embed_w = (const float*)d_in[2];
    const float* conv_w  = (const float*)d_in[3];
    const float* conv_b  = (const float*)d_in[4];
    const float* U_w     = (const float*)d_in[5];
    const float* fc_w    = (const float*)d_in[6];
    const float* fc_b    = (const float*)d_in[7];
    float* out = (float*)d_out;   // [0..15999] logits, [16000] loss

    static int smem_set = 0;
    if (!smem_set) {
        cudaFuncSetAttribute(mega_kernel,
                             cudaFuncAttributeMaxDynamicSharedMemorySize, FUSE_SMEM);
        smem_set = 1;
    }

    // 1) MEGA: prep + conv + attn, dependency-gated
    mega_kernel<<<NBLK, 256, FUSE_SMEM>>>(x, embed_w, conv_w, U_w, fc_w, conv_b);

    // 2) merge partials -> logits (+ zero loss slot)
    part_reduce_kernel<<<(B_ * Y_) / 8, 256>>>(fc_b, out);

    // 3) cross-entropy loss (per-batch, atomic accumulate) + state reset
    nll_kernel<<<B_, 256>>>(out, target, out + B_ * Y_);
}

// round 17
// speedup vs baseline: 1.1071x; 1.1071x over previous
#include <cuda_runtime.h>
#include <cuda_fp16.h>
#include <math.h>

#define B_  16
#define L_  4096
#define E_  128
#define F_  256
#define Y_  1000
#define YP_ 1024
#define MP_ 2048             /* padded, interleaved attn M */

#define BM  128
#define BN  128
#define BK  64               /* halves per K chunk */
#define SROWH 72             /* staging row stride in halves (144B) */
#define STAGEH (BM * SROWH)  /* stage halves = 9216 */
#define NSTAGE 3
#define CV_SMEM (2 * NSTAGE * STAGEH * 2)   /* conv: A+B, 3 stages = 110592 B */

/* attn: B resident (128 x 264 halves) + A 2-stage (128 x 72 halves each) */
#define SROWB 264
#define AT_BH (BN * SROWB)                   /* 33792 halves */
#define AT_SMEM ((AT_BH + 2 * STAGEH) * 2)   /* 104448 B */

#define FUSE_SMEM (CV_SMEM > AT_SMEM ? CV_SMEM : AT_SMEM)
#define NCONV 1024           /* conv blocks in fused launch */

// Scratch (static __device__ arrays; allocation-free per harness rules)
__device__ __align__(128) __half g_embH[(size_t)B_ * L_ * E_];  // fp16 embeddings
__device__ __align__(128) __half g_wH  [3 * F_ * E_];           // fp16 conv_w [kw][f][e]
__device__ __align__(128) __half g_w2H [(size_t)MP_ * F_];      // interleaved [U;fc] rows
__device__ __align__(128) __half g_hcH [(size_t)B_ * L_ * F_];  // conv out fp16 [b][l][f]
__device__ __align__(128) float  g_part[(size_t)B_ * YP_ * 64 * 3]; // (m,Z,S) partials
__device__ int g_flag[B_ * 32];                                  // conv tile-ready flags

// ---------------------------------------------------------------------------
__device__ __forceinline__ unsigned smem_u32(const void* p) {
    unsigned a;
    asm("{ .reg .u64 t; cvta.to.shared.u64 t, %1; cvt.u32.u64 %0, t; }"
        : "=r"(a) : "l"(p));
    return a;
}
__device__ __forceinline__ void cp_async16(unsigned dst, const void* src, int src_bytes) {
    asm volatile("cp.async.cg.shared.global [%0], [%1], 16, %2;"
                 :: "r"(dst), "l"(src), "r"(src_bytes));
}
__device__ __forceinline__ void cp_commit() {
    asm volatile("cp.async.commit_group;");
}
__device__ __forceinline__ void ldsm4(unsigned* r, unsigned addr) {
    asm volatile("ldmatrix.sync.aligned.m8n8.x4.shared.b16 {%0,%1,%2,%3}, [%4];"
                 : "=r"(r[0]), "=r"(r[1]), "=r"(r[2]), "=r"(r[3]) : "r"(addr));
}
__device__ __forceinline__ void mma16816(float* d, const unsigned* a, const unsigned* b) {
    asm volatile(
        "mma.sync.aligned.m16n8k16.row.col.f32.f16.f16.f32 "
        "{%0,%1,%2,%3}, {%4,%5,%6,%7}, {%8,%9}, {%0,%1,%2,%3};"
        : "+f"(d[0]), "+f"(d[1]), "+f"(d[2]), "+f"(d[3])
        : "r"(a[0]), "r"(a[1]), "r"(a[2]), "r"(a[3]), "r"(b[0]), "r"(b[1]));
}

// ---------------------------------------------------------------------------
// Kernel 1 (fused producers): blocks [0,8192) embed gather; [8192,8320) conv_w
// transpose; [8320,8832) interleaved weight stack. Block 8320 also zeroes the
// conv tile flags. All fp16-rounded.
// ---------------------------------------------------------------------------
__global__ void prep_kernel(const int* __restrict__ x,
                            const float* __restrict__ embed_w,
                            const float* __restrict__ conv_w,
                            const float* __restrict__ U_w,
                            const float* __restrict__ fc_w)
{
    int blk = blockIdx.x;
    if (blk < 8192) {
        int b = blk >> 9;
        int l = (blk & 511) * 8 + (threadIdx.x >> 5);
        int q = threadIdx.x & 31;
        int xi = x[b * L_ + l];
        float4 v = ((const float4*)(embed_w + (size_t)xi * E_))[q];
        __half2 h01 = __floats2half2_rn(v.x, v.y);
        __half2 h23 = __floats2half2_rn(v.z, v.w);
        uint2 u;
        u.x = *(unsigned*)&h01;
        u.y = *(unsigned*)&h23;
        ((uint2*)(g_embH + ((size_t)b * L_ + l) * E_))[q] = u;
    } else if (blk < 8320) {
        int i = (blk - 8192) * 256 + threadIdx.x;
        if (i < F_ * E_) {
            int f = i / E_, e = i % E_;
            #pragma unroll
            for (int kw = 0; kw < 3; kw++)
                g_wH[((size_t)kw * F_ + f) * E_ + e] =
                    __float2half_rn(conv_w[((size_t)f * E_ + e) * 3 + kw]);
        }
    } else {
        if (blk == 8320) {
            g_flag[threadIdx.x] = 0;
            g_flag[threadIdx.x + 256] = 0;
        }
        int i = (blk - 8320) * 256 + threadIdx.x;
        if (i < MP_ * F_ / 4) {
            int r = i / (F_ / 4), c4 = i % (F_ / 4);
            float4 v = make_float4(0.f, 0.f, 0.f, 0.f);
            if (r < 2 * Y_) {
                int y = r >> 1;
                const float* src = (r & 1) ? fc_w : U_w;
                v = ((const float4*)(src + (size_t)y * F_))[c4];
            }
            __half2 h01 = __floats2half2_rn(v.x, v.y);
            __half2 h23 = __floats2half2_rn(v.z, v.w);
            uint2 u;
            u.x = *(unsigned*)&h01;
            u.y = *(unsigned*)&h23;
            ((uint2*)(g_w2H + (size_t)r * F_))[c4] = u;
        }
    }
}

// ---------------------------------------------------------------------------
// Kernel 2 (FUSED conv+attn, 3072 blocks):
//  bids [0,1024): conv (R11-proven body). Order: b-major (bid = b*64 + y*32 + x).
//     After epilogue: threadfence + atomicAdd(flag[b*32+x]) (2 arrivals/tile).
//  bids [1024,3072): attn (R11-proven body). Order b-major. Spins on
//     flag[b*32+ltile]==2 before loading its B tile.
// ---------------------------------------------------------------------------
__global__ __launch_bounds__(256)
void gemm_fused_kernel(const float* __restrict__ bias)
{
    extern __shared__ __align__(16) char smem[];

    int tid  = threadIdx.x;
    int wid  = tid >> 5, lane = tid & 31;
    int g    = lane >> 2, tig = lane & 3;
    int lq   = lane >> 3, lr  = lane & 7;
    int wm   = wid >> 1,  wn  = wid & 1;

    if (blockIdx.x < NCONV) {
        // =================== CONV path ===================
        unsigned aBase = smem_u32(smem);
        unsigned bBase = aBase + NSTAGE * STAGEH * 2;

        int blk = blockIdx.x;
        int xt  = blk & 31;            // l-tile
        int yt  = (blk >> 5) & 1;      // f-tile
        int b   = blk >> 6;
        int m0  = xt * BM, n0 = yt * BN;
        const int nchunks = 6;

        int lrow  = tid >> 1;
        int lcolh = (tid & 1) * 32;

        float d[2][8][4];
        #pragma unroll
        for (int mi = 0; mi < 2; mi++)
            #pragma unroll
            for (int ni = 0; ni < 8; ni++)
                #pragma unroll
                for (int q = 0; q < 4; q++) d[mi][ni][q] = 0.0f;

        auto prefetch = [&](int c) {
            int st = c % NSTAGE;
            int kw = c >> 1, ek = (c & 1) * BK;
            int lsrc = m0 + lrow + kw - 1;
            bool av = ((unsigned)lsrc < (unsigned)L_);
            int abytes = av ? 16 : 0;
            const __half* ap = g_embH + ((size_t)b * L_ + (av ? lsrc : 0)) * E_ + ek + lcolh;
            const __half* bp = g_wH + ((size_t)kw * F_ + n0 + lrow) * E_ + ek + lcolh;
            unsigned da = aBase + (st * STAGEH + lrow * SROWH + lcolh) * 2;
            unsigned db = bBase + (st * STAGEH + lrow * SROWH + lcolh) * 2;
            #pragma unroll
            for (int j = 0; j < 4; j++) {
                cp_async16(da + j * 16, ap + j * 8, abytes);
                cp_async16(db + j * 16, bp + j * 8, 16);
            }
        };

        prefetch(0); cp_commit();
        prefetch(1); cp_commit();

        unsigned aOffs[2], bOffs[4];
        #pragma unroll
        for (int mi = 0; mi < 2; mi++) {
            int row = wm * 32 + mi * 16 + (lq & 1) * 8 + lr;
            aOffs[mi] = (row * SROWH + (lq >> 1) * 8) * 2;
        }
        #pragma unroll
        for (int ti = 0; ti < 4; ti++) {
            int row = wn * 64 + ti * 16 + (lq >> 1) * 8 + lr;
            bOffs[ti] = (row * SROWH + (lq & 1) * 8) * 2;
        }

        for (int c = 0; c < nchunks; c++) {
            if (c + 1 < nchunks) asm volatile("cp.async.wait_group 1;");
            else                 asm volatile("cp.async.wait_group 0;");
            __syncthreads();
            if (c + 2 < nchunks) { prefetch(c + 2); cp_commit(); }

            int st = c % NSTAGE;
            unsigned Ab = aBase + st * STAGEH * 2;
            unsigned Bb = bBase + st * STAGEH * 2;

            #pragma unroll
            for (int kk = 0; kk < 4; kk++) {
                unsigned af[2][4];
                #pragma unroll
                for (int mi = 0; mi < 2; mi++)
                    ldsm4(af[mi], Ab + aOffs[mi] + kk * 32);
                unsigned bf[4][4];
                #pragma unroll
                for (int ti = 0; ti < 4; ti++)
                    ldsm4(bf[ti], Bb + bOffs[ti] + kk * 32);
                #pragma unroll
                for (int mi = 0; mi < 2; mi++)
                    #pragma unroll
                    for (int ni = 0; ni < 8; ni++)
                        mma16816(d[mi][ni], af[mi], &bf[ni >> 1][(ni & 1) * 2]);
            }
        }

        #pragma unroll
        for (int mi = 0; mi < 2; mi++) {
            int row = m0 + wm * 32 + mi * 16 + g;
            #pragma unroll
            for (int ni = 0; ni < 8; ni++) {
                int col = n0 + wn * 64 + ni * 8 + tig * 2;
                float b0 = bias[col], b1 = bias[col + 1];
                __half2 v0 = __floats2half2_rn(fmaxf(d[mi][ni][0] + b0, 0.f),
                                               fmaxf(d[mi][ni][1] + b1, 0.f));
                __half2 v1 = __floats2half2_rn(fmaxf(d[mi][ni][2] + b0, 0.f),
                                               fmaxf(d[mi][ni][3] + b1, 0.f));
                *(__half2*)(g_hcH + ((size_t)b * L_ + row) * F_ + col)     = v0;
                *(__half2*)(g_hcH + ((size_t)b * L_ + row + 8) * F_ + col) = v1;
            }
        }

        // publish tile: both y-halves must arrive before attn consumes rows
        __syncthreads();
        __threadfence();
        if (tid == 0) atomicAdd(&g_flag[b * 32 + xt], 1);

    } else {
        // =================== ATTN path ===================
        unsigned bBase = smem_u32(smem);                 // B: 128 x SROWB halves
        unsigned aBase = bBase + AT_BH * 2;              // A: 2 x STAGEH halves

        int ab    = blockIdx.x - NCONV;
        int ltile = ab & 31;
        int mgrp  = (ab >> 5) & 3;
        int b     = ab >> 7;
        int n0    = ltile * BN;
        int mg0   = mgrp * 4 * BM;

        // wait for conv tile (b, ltile): 2 producer blocks
        if (tid == 0) {
            while (atomicAdd(&g_flag[b * 32 + ltile], 0) < 2)
                __nanosleep(64);
        }
        __syncthreads();

        int lrow  = tid >> 1;
        int lcolh = (tid & 1) * 32;

        // ---- issue B tile load: 128 rows x 256 halves, 2 threads/row ----
        {
            const __half* bp = g_hcH + ((size_t)b * L_ + n0 + lrow) * F_ + (tid & 1) * 128;
            unsigned db = bBase + (lrow * SROWB + (tid & 1) * 128) * 2;
            #pragma unroll
            for (int j = 0; j < 16; j++)
                cp_async16(db + j * 16, bp + j * 8, 16);
        }
        cp_commit();

        auto prefetchA = [&](int q) {
            int i = q >> 2, kc = q & 3;
            const __half* ap = g_w2H + (size_t)(mg0 + i * BM + lrow) * F_ + kc * BK + lcolh;
            unsigned da = aBase + ((q & 1) * STAGEH + lrow * SROWH + lcolh) * 2;
            #pragma unroll
            for (int j = 0; j < 4; j++)
                cp_async16(da + j * 16, ap + j * 8, 16);
        };

        prefetchA(0);
        cp_commit();

        unsigned aOffs[2], bOffs[4];
        #pragma unroll
        for (int mi = 0; mi < 2; mi++) {
            int row = wm * 32 + mi * 16 + (lq & 1) * 8 + lr;
            aOffs[mi] = (row * SROWH + (lq >> 1) * 8) * 2;
        }
        #pragma unroll
        for (int ti = 0; ti < 4; ti++) {
            int row = wn * 64 + ti * 16 + (lq >> 1) * 8 + lr;
            bOffs[ti] = (row * SROWB + (lq & 1) * 8) * 2;
        }

        int p = ltile * 2 + wn;        // 64-l chunk index (0..63)
        float d[2][8][4];

        for (int q = 0; q < 16; q++) {
            int kc = q & 3;
            if (kc == 0) {
                #pragma unroll
                for (int mi = 0; mi < 2; mi++)
                    #pragma unroll
                    for (int ni = 0; ni < 8; ni++)
                        #pragma unroll
                        for (int u = 0; u < 4; u++) d[mi][ni][u] = 0.0f;
            }

            asm volatile("cp.async.wait_group 0;");
            __syncthreads();
            if (q + 1 < 16) { prefetchA(q + 1); cp_commit(); }

            unsigned Ab = aBase + (q & 1) * STAGEH * 2;
            unsigned Bc = bBase + kc * BK * 2;

            #pragma unroll
            for (int kk = 0; kk < 4; kk++) {
                unsigned af[2][4];
                #pragma unroll
                for (int mi = 0; mi < 2; mi++)
                    ldsm4(af[mi], Ab + aOffs[mi] + kk * 32);
                unsigned bf[4][4];
                #pragma unroll
                for (int ti = 0; ti < 4; ti++)
                    ldsm4(bf[ti], Bc + bOffs[ti] + kk * 32);
                #pragma unroll
                for (int mi = 0; mi < 2; mi++)
                    #pragma unroll
                    for (int ni = 0; ni < 8; ni++)
                        mma16816(d[mi][ni], af[mi], &bf[ni >> 1][(ni & 1) * 2]);
            }

            if (kc == 3) {
                int m0 = mg0 + (q >> 2) * BM;
                #pragma unroll
                for (int mi = 0; mi < 2; mi++) {
                    float td[8][4];
                    #pragma unroll
                    for (int ni = 0; ni < 8; ni++)
                        #pragma unroll
                        for (int u = 0; u < 4; u++)
                            td[ni][u] = __shfl_down_sync(0xFFFFFFFFu, d[mi][ni][u], 4);

                    if ((g & 1) == 0) {
                        #pragma unroll
                        for (int h = 0; h < 2; h++) {
                            float mm = -1e30f, Z = 0.f, S = 0.f;
                            #pragma unroll
                            for (int ni = 0; ni < 8; ni++) {
                                #pragma unroll
                                for (int cq = 0; cq < 2; cq++) {
                                    float sv = d[mi][ni][h * 2 + cq];
                                    float tv = td[ni][h * 2 + cq];
                                    if (sv > mm) {
                                        float r = __expf(mm - sv);
                                        Z *= r; S *= r; mm = sv;
                                    }
                                    float e = __expf(sv - mm);
                                    Z += e; S += e * tv;
                                }
                            }
                            const unsigned qmask = 0x0F0F0F0Fu;
                            #pragma unroll
                            for (int off = 1; off <= 2; off <<= 1) {
                                float m2 = __shfl_xor_sync(qmask, mm, off);
                                float Z2 = __shfl_xor_sync(qmask, Z, off);
                                float S2 = __shfl_xor_sync(qmask, S, off);
                                float mn = fmaxf(mm, m2);
                                float r1 = __expf(mm - mn), r2 = __expf(m2 - mn);
                                Z = Z * r1 + Z2 * r2;
                                S = S * r1 + S2 * r2;
                                mm = mn;
                            }
                            if (tig == 0) {
                                int y = (m0 + wm * 32 + mi * 16 + g + 8 * h) >> 1;
                                float* dst = g_part + ((size_t)(b * YP_ + y) * 64 + p) * 3;
                                dst[0] = mm; dst[1] = Z; dst[2] = S;
                            }
                        }
                    }
                }
            }
        }
    }
}

// ---------------------------------------------------------------------------
// Kernel 3: merge 64 softmax partials per (b,y) -> logits; zero loss slot.
// ---------------------------------------------------------------------------
__global__ void part_reduce_kernel(const float* __restrict__ fc_b,
                                   float* __restrict__ out_logit)
{
    if (blockIdx.x == 0 && threadIdx.x == 0)
        out_logit[B_ * Y_] = 0.0f;          // zero loss accumulator

    int idx = blockIdx.x * 8 + (threadIdx.x >> 5);   // 0..15999
    int b = idx / Y_, y = idx % Y_;
    const float* pp = g_part + ((size_t)(b * YP_ + y) * 64) * 3;
    int lane = threadIdx.x & 31;

    float m = pp[lane * 3], Z = pp[lane * 3 + 1], S = pp[lane * 3 + 2];
    {
        float m2 = pp[(lane + 32) * 3], Z2 = pp[(lane + 32) * 3 + 1], S2 = pp[(lane + 32) * 3 + 2];
        float mn = fmaxf(m, m2);
        float r1 = __expf(m - mn), r2 = __expf(m2 - mn);
        Z = Z * r1 + Z2 * r2; S = S * r1 + S2 * r2; m = mn;
    }
    #pragma unroll
    for (int off = 16; off; off >>= 1) {
        float m2 = __shfl_xor_sync(0xFFFFFFFFu, m, off);
        float Z2 = __shfl_xor_sync(0xFFFFFFFFu, Z, off);
        float S2 = __shfl_xor_sync(0xFFFFFFFFu, S, off);
        float mn = fmaxf(m, m2);
        float r1 = __expf(m - mn), r2 = __expf(m2 - mn);
        Z = Z * r1 + Z2 * r2; S = S * r1 + S2 * r2; m = mn;
    }
    if (lane == 0) out_logit[b * Y_ + y] = S / Z + fc_b[y];
}

// ---------------------------------------------------------------------------
// Kernel 4: per-batch NLL, atomically accumulated into out[16000].
// ---------------------------------------------------------------------------
__global__ void nll_kernel(const float* __restrict__ logit,
                           const int* __restrict__ target,
                           float* __restrict__ loss_out)
{
    __shared__ float red[256];
    int b = blockIdx.x;
    int tid = threadIdx.x;
    const float* lr = logit + b * Y_;

    float mx = -1e30f;
    for (int i = tid; i < Y_; i += 256) mx = fmaxf(mx, lr[i]);
    red[tid] = mx; __syncthreads();
    for (int s = 128; s; s >>= 1) {
        if (tid < s) red[tid] = fmaxf(red[tid], red[tid + s]);
        __syncthreads();
    }
    mx = red[0]; __syncthreads();

    float se = 0.0f;
    for (int i = tid; i < Y_; i += 256) se += expf(lr[i] - mx);
    red[tid] = se; __syncthreads();
    for (int s = 128; s; s >>= 1) {
        if (tid < s) red[tid] += red[tid + s];
        __syncthreads();
    }
    if (tid == 0) {
        float lp = lr[target[b]] - mx - logf(red[0]);
        atomicAdd(loss_out, -lp / (float)B_);
    }
}

// ---------------------------------------------------------------------------
extern "C" void kernel_launch(void* const* d_in, const int* in_sizes, int n_in,
                              void* d_out, int out_size)
{
    const int*   x       = (const int*)  d_in[0];
    const int*   target  = (const int*)  d_in[1];
    const float* embed_w = (const float*)d_in[2];
    const float* conv_w  = (const float*)d_in[3];
    const float* conv_b  = (const float*)d_in[4];
    const float* U_w     = (const float*)d_in[5];
    const float* fc_w    = (const float*)d_in[6];
    const float* fc_b    = (const float*)d_in[7];
    float* out = (float*)d_out;   // [0..15999] logits, [16000] loss

    static int smem_set = 0;
    if (!smem_set) {
        cudaFuncSetAttribute(gemm_fused_kernel,
                             cudaFuncAttributeMaxDynamicSharedMemorySize, FUSE_SMEM);
        smem_set = 1;
    }

    // 1) fused producers (also zeroes tile flags)
    prep_kernel<<<8832, 256>>>(x, embed_w, conv_w, U_w, fc_w);

    // 2+3) fused conv + attn with tile-flag overlap
    gemm_fused_kernel<<<NCONV + 2048, 256, FUSE_SMEM>>>(conv_b);

    // 4) merge partials -> logits (+ zero loss slot)
    part_reduce_kernel<<<(B_ * Y_) / 8, 256>>>(fc_b, out);

    // 5) cross-entropy loss (per-batch, atomic accumulate)
    nll_kernel<<<B_, 256>>>(out, target, out + B_ * Y_);
}